// round 1
// baseline (speedup 1.0000x reference)
#include <cuda_runtime.h>

typedef unsigned long long u64;

#define NTOK 8192
#define NQB  6
#define DIM  64            // 2^6 amplitudes
#define NSPLIT 16
#define BM 128
#define BN 64
#define TM 8
#define TN 4
#define QPAD 65
#define KPAD 65
#define KEYS_PER_SPLIT (NTOK / NSPLIT)   // 512

// ---------------- device scratch (no allocations allowed) ----------------
__device__ __align__(16) float2 g_q[NTOK * DIM];
__device__ __align__(16) float2 g_k[NTOK * DIM];
__device__ float g_v[NTOK * NQB];
__device__ float g_part[(size_t)NSPLIT * NTOK * 8];

// ---------------- packed f32x2 helpers ----------------
__device__ __forceinline__ u64 pack2(float lo, float hi) {
    u64 r;
    asm("mov.b64 %0, {%1, %2};" : "=l"(r) : "f"(lo), "f"(hi));
    return r;
}
__device__ __forceinline__ void unpack2(u64 v, float& lo, float& hi) {
    asm("mov.b64 {%0, %1}, %2;" : "=f"(lo), "=f"(hi) : "l"(v));
}
__device__ __forceinline__ u64 fma2(u64 a, u64 b, u64 c) {
    u64 d;
    asm("fma.rn.f32x2 %0, %1, %2, %3;" : "=l"(d) : "l"(a), "l"(b), "l"(c));
    return d;
}

// ---------------- quantum gates: one warp = one token ----------------
// amplitude d in [0,64): lane = d>>1 owns (a0 = amp(2*lane), a1 = amp(2*lane+1)).
// qubit q bit of d is (d >> (5-q)) & 1 ; qubits 0..4 live in lane bits, qubit 5 is local.

__device__ __forceinline__ void ry_gate(float th, int q, int lane,
        float& a0x, float& a0y, float& a1x, float& a1y)
{
    float s, c;
    sincosf(0.5f * th, &s, &c);
    if (q == 5) {
        float n0x = c*a0x - s*a1x, n0y = c*a0y - s*a1y;
        float n1x = s*a0x + c*a1x, n1y = s*a0y + c*a1y;
        a0x = n0x; a0y = n0y; a1x = n1x; a1y = n1y;
    } else {
        int sh = 4 - q, m = 1 << sh;
        float o0x = __shfl_xor_sync(0xffffffffu, a0x, m);
        float o0y = __shfl_xor_sync(0xffffffffu, a0y, m);
        float o1x = __shfl_xor_sync(0xffffffffu, a1x, m);
        float o1y = __shfl_xor_sync(0xffffffffu, a1y, m);
        float sg = ((lane >> sh) & 1) ? s : -s;   // bit0: c*me - s*other ; bit1: c*me + s*other
        a0x = c*a0x + sg*o0x; a0y = c*a0y + sg*o0y;
        a1x = c*a1x + sg*o1x; a1y = c*a1y + sg*o1y;
    }
}

__device__ __forceinline__ void rz_gate(float th, int q, int lane,
        float& a0x, float& a0y, float& a1x, float& a1y)
{
    float s, c;
    sincosf(0.5f * th, &s, &c);
    if (q == 5) {
        // a0 (bit 0): *(c - i s) ; a1 (bit 1): *(c + i s)
        float n0x = a0x*c + a0y*s, n0y = a0y*c - a0x*s;
        float n1x = a1x*c - a1y*s, n1y = a1y*c + a1x*s;
        a0x = n0x; a0y = n0y; a1x = n1x; a1y = n1y;
    } else {
        float t = ((lane >> (4 - q)) & 1) ? s : -s;  // *(c + i t)
        float n0x = a0x*c - a0y*t, n0y = a0y*c + a0x*t;
        float n1x = a1x*c - a1y*t, n1y = a1y*c + a1x*t;
        a0x = n0x; a0y = n0y; a1x = n1x; a1y = n1y;
    }
}

// CNOT with both control and target in lane bits: control shift csh, target lane-mask tmask
__device__ __forceinline__ void cnot_ll(int csh, int tmask, int lane,
        float& a0x, float& a0y, float& a1x, float& a1y)
{
    float o0x = __shfl_xor_sync(0xffffffffu, a0x, tmask);
    float o0y = __shfl_xor_sync(0xffffffffu, a0y, tmask);
    float o1x = __shfl_xor_sync(0xffffffffu, a1x, tmask);
    float o1y = __shfl_xor_sync(0xffffffffu, a1y, tmask);
    if ((lane >> csh) & 1) { a0x = o0x; a0y = o0y; a1x = o1x; a1y = o1y; }
}

__global__ void prep_kernel(const float* __restrict__ x,
                            const float* __restrict__ pq,
                            const float* __restrict__ pk,
                            const float* __restrict__ pv)
{
    int gw   = (blockIdx.x * blockDim.x + threadIdx.x) >> 5;
    int lane = threadIdx.x & 31;
    int set  = gw >> 13;            // 0 = Q, 1 = K, 2 = V   (gw / 8192)
    int tok  = gw & (NTOK - 1);
    const float* prm = (set == 0) ? pq : (set == 1) ? pk : pv;

    float a0x = (lane == 0) ? 1.f : 0.f, a0y = 0.f, a1x = 0.f, a1y = 0.f;

    // RY angle embedding
    #pragma unroll
    for (int q = 0; q < 6; q++)
        ry_gate(x[tok * 6 + q], q, lane, a0x, a0y, a1x, a1y);

    // PQC layers
    #pragma unroll
    for (int l = 0; l < 2; l++) {
        #pragma unroll
        for (int q = 0; q < 6; q++) {
            ry_gate(prm[(l * 6 + q) * 2 + 0], q, lane, a0x, a0y, a1x, a1y);
            rz_gate(prm[(l * 6 + q) * 2 + 1], q, lane, a0x, a0y, a1x, a1y);
        }
        // CNOT ring (0,1)(1,2)(2,3)(3,4)(4,5)(5,0)
        cnot_ll(4, 8, lane, a0x, a0y, a1x, a1y);   // (0,1)
        cnot_ll(3, 4, lane, a0x, a0y, a1x, a1y);   // (1,2)
        cnot_ll(2, 2, lane, a0x, a0y, a1x, a1y);   // (2,3)
        cnot_ll(1, 1, lane, a0x, a0y, a1x, a1y);   // (3,4)
        if (lane & 1) {                            // (4,5): ctrl = lane bit0, tgt local
            float t;
            t = a0x; a0x = a1x; a1x = t;
            t = a0y; a0y = a1y; a1y = t;
        }
        // (5,0): ctrl local bit (a1), flip lane bit4
        a1x = __shfl_xor_sync(0xffffffffu, a1x, 16);
        a1y = __shfl_xor_sync(0xffffffffu, a1y, 16);
    }

    if (set == 0) {
        ((float4*)g_q)[tok * 32 + lane] = make_float4(a0x, a0y, a1x, a1y);
    } else if (set == 1) {
        ((float4*)g_k)[tok * 32 + lane] = make_float4(a0x, a0y, a1x, a1y);
    } else {
        // V[tok][q] = sum_d |amp_d|^2 * (1 - 2*bit_q(d))
        float p0 = a0x*a0x + a0y*a0y;
        float p1 = a1x*a1x + a1y*a1y;
        int d0 = lane * 2, d1 = lane * 2 + 1;
        #pragma unroll
        for (int q = 0; q < 6; q++) {
            float s0 = ((d0 >> (5 - q)) & 1) ? -1.f : 1.f;
            float s1 = ((d1 >> (5 - q)) & 1) ? -1.f : 1.f;
            float z = s0 * p0 + s1 * p1;
            #pragma unroll
            for (int o = 16; o; o >>= 1) z += __shfl_xor_sync(0xffffffffu, z, o);
            if (lane == 0) g_v[tok * 6 + q] = z;
        }
    }
}

// ---------------- flash attention (single-pass: logits in [0,1], no max needed) ----
// e^x on [0,1.01]: degree-7 Taylor, abs err < 7e-5 — avoids MUFU EX2 throughput wall.
__device__ __forceinline__ float exp_poly(float v)
{
    float p = 1.9841269841e-4f;           // 1/5040
    p = fmaf(p, v, 1.3888888889e-3f);     // 1/720
    p = fmaf(p, v, 8.3333333333e-3f);     // 1/120
    p = fmaf(p, v, 4.1666666667e-2f);     // 1/24
    p = fmaf(p, v, 1.6666666667e-1f);     // 1/6
    p = fmaf(p, v, 0.5f);
    p = fmaf(p, v, 1.0f);
    p = fmaf(p, v, 1.0f);
    return p;
}

extern __shared__ u64 sm_dyn[];

__global__ void __launch_bounds__(256, 1) attn_kernel()
{
    u64*   Qs = sm_dyn;                       // [BM][QPAD] (qr,qi) row-major, broadcast reads
    u64*   Ks = Qs + BM * QPAD;               // [DIM][KPAD] transposed, bank = 2*tx (conflict-free)
    float* Vs = (float*)(Ks + DIM * KPAD);    // [BN][6]

    int tid = threadIdx.x;
    int tx  = tid & 15, ty = tid >> 4;
    int qbase  = blockIdx.x * BM;
    int kbase0 = blockIdx.y * KEYS_PER_SPLIT;

    const u64* gq = (const u64*)g_q;
    const u64* gk = (const u64*)g_k;

    #pragma unroll
    for (int e = 0; e < (BM * DIM) / 256; e++) {      // Q tile loaded once per block
        int flat = e * 256 + tid;
        int row = flat >> 6, d = flat & 63;
        Qs[row * QPAD + d] = gq[(size_t)(qbase + row) * DIM + d];
    }

    float den[TM];
    float num[TM][6];
    #pragma unroll
    for (int m = 0; m < TM; m++) {
        den[m] = 0.f;
        #pragma unroll
        for (int c = 0; c < 6; c++) num[m][c] = 0.f;
    }

    for (int kt = 0; kt < KEYS_PER_SPLIT / BN; kt++) {
        int kb = kbase0 + kt * BN;
        __syncthreads();
        #pragma unroll
        for (int e = 0; e < (BN * DIM) / 256; e++) {  // transpose K into smem
            int flat = e * 256 + tid;
            int d = flat & 63, j = flat >> 6;
            Ks[d * KPAD + j] = gk[(size_t)(kb + j) * DIM + d];
        }
        for (int i = tid; i < BN * 6; i += 256) Vs[i] = g_v[kb * 6 + i];
        __syncthreads();

        u64 acc[TM][TN];
        #pragma unroll
        for (int m = 0; m < TM; m++)
            #pragma unroll
            for (int n = 0; n < TN; n++) acc[m][n] = 0ull;

        const u64* qp = Qs + ty * QPAD;   // rows ty + 16*m
        const u64* kp = Ks + tx;          // keys tx + 16*n

        // complex MAC as 2x FFMA2: acc=(re,im); (qr,qi)*(kr,kr) then (qi,-qr)*(ki,ki)
        #pragma unroll 8
        for (int d = 0; d < DIM; d++) {
            u64 A[TM], B[TM];
            #pragma unroll
            for (int m = 0; m < TM; m++) {
                u64 a = qp[m * (16 * QPAD) + d];
                A[m] = a;
                float axr, axi; unpack2(a, axr, axi);
                B[m] = pack2(axi, -axr);
            }
            u64 KR[TN], KI[TN];
            #pragma unroll
            for (int n = 0; n < TN; n++) {
                u64 kv = kp[d * KPAD + n * 16];
                float kr, ki; unpack2(kv, kr, ki);
                KR[n] = pack2(kr, kr);
                KI[n] = pack2(ki, ki);
            }
            #pragma unroll
            for (int m = 0; m < TM; m++)
                #pragma unroll
                for (int n = 0; n < TN; n++) {
                    acc[m][n] = fma2(A[m], KR[n], acc[m][n]);
                    acc[m][n] = fma2(B[m], KI[n], acc[m][n]);
                }
        }

        #pragma unroll
        for (int n = 0; n < TN; n++) {
            const float* vv = Vs + (tx + 16 * n) * 6;
            float v0 = vv[0], v1 = vv[1], v2 = vv[2], v3 = vv[3], v4 = vv[4], v5 = vv[5];
            #pragma unroll
            for (int m = 0; m < TM; m++) {
                float re, im; unpack2(acc[m][n], re, im);
                float lg = fmaf(re, re, im * im);     // fidelity in [0,1]
                float p = exp_poly(lg);
                den[m] += p;
                num[m][0] = fmaf(p, v0, num[m][0]);
                num[m][1] = fmaf(p, v1, num[m][1]);
                num[m][2] = fmaf(p, v2, num[m][2]);
                num[m][3] = fmaf(p, v3, num[m][3]);
                num[m][4] = fmaf(p, v4, num[m][4]);
                num[m][5] = fmaf(p, v5, num[m][5]);
            }
        }
    }

    // reduce over tx (16 lanes within each half-warp; xor offsets < 16 stay in-half)
    #pragma unroll
    for (int m = 0; m < TM; m++) {
        #pragma unroll
        for (int o = 8; o; o >>= 1) {
            den[m] += __shfl_xor_sync(0xffffffffu, den[m], o);
            #pragma unroll
            for (int c = 0; c < 6; c++)
                num[m][c] += __shfl_xor_sync(0xffffffffu, num[m][c], o);
        }
    }
    if (tx == 0) {
        #pragma unroll
        for (int m = 0; m < TM; m++) {
            int q = qbase + ty + 16 * m;
            float* p = g_part + ((size_t)blockIdx.y * NTOK + q) * 8;
            #pragma unroll
            for (int c = 0; c < 6; c++) p[c] = num[m][c];
            p[6] = den[m];
        }
    }
}

__global__ void finalize_kernel(float* __restrict__ out)
{
    int i = blockIdx.x * blockDim.x + threadIdx.x;
    float acc0 = 0.f, acc1 = 0.f, acc2 = 0.f, acc3 = 0.f, acc4 = 0.f, acc5 = 0.f, den = 0.f;
    #pragma unroll
    for (int s = 0; s < NSPLIT; s++) {
        const float* p = g_part + ((size_t)s * NTOK + i) * 8;
        acc0 += p[0]; acc1 += p[1]; acc2 += p[2];
        acc3 += p[3]; acc4 += p[4]; acc5 += p[5];
        den  += p[6];
    }
    float inv = 1.0f / den;
    out[i * 6 + 0] = acc0 * inv;
    out[i * 6 + 1] = acc1 * inv;
    out[i * 6 + 2] = acc2 * inv;
    out[i * 6 + 3] = acc3 * inv;
    out[i * 6 + 4] = acc4 * inv;
    out[i * 6 + 5] = acc5 * inv;
}

extern "C" void kernel_launch(void* const* d_in, const int* in_sizes, int n_in,
                              void* d_out, int out_size)
{
    const float* x  = (const float*)d_in[0];
    const float* pq = (const float*)d_in[1];
    const float* pk = (const float*)d_in[2];
    const float* pv = (const float*)d_in[3];

    // 3*8192 warps -> 3072 blocks of 256 threads
    prep_kernel<<<(3 * NTOK) / 8, 256>>>(x, pq, pk, pv);

    size_t sh = (size_t)(BM * QPAD + DIM * KPAD) * sizeof(u64) + (size_t)BN * 6 * sizeof(float);
    cudaFuncSetAttribute(attn_kernel, cudaFuncAttributeMaxDynamicSharedMemorySize, (int)sh);
    attn_kernel<<<dim3(NTOK / BM, NSPLIT), 256, sh>>>();

    finalize_kernel<<<NTOK / 256, 256>>>((float*)d_out);
}

// round 6
// speedup vs baseline: 4.4380x; 4.4380x over previous
#include <cuda_runtime.h>
#include <cuda_fp16.h>
#include <cstdint>

typedef unsigned long long u64;

#define NTOK 8192
#define NQB  6
#define NSPLIT 2
#define KEYS_PER_SPLIT (NTOK / NSPLIT)   // 4096
#define BN 64                            // keys per chunk
#define CHUNKS (KEYS_PER_SPLIT / BN)     // 64
#define PITCH 272                        // 256B row + 16B pad (ldmatrix bank-conflict-free)

// ---- smem layout (bytes) ----
#define A_OFF     0
#define A_BYTES   (128 * PITCH)                      // 34816
#define BRE_OFF(p) (A_BYTES + (p) * (2 * 64 * PITCH))
#define BIM_OFF(p) (BRE_OFF(p) + 64 * PITCH)
#define V_OFF(p)  (A_BYTES + 2 * (2 * 64 * PITCH) + (p) * 2048)   // 64 keys x 8 floats
#define RED_OFF   (A_BYTES + 2 * (2 * 64 * PITCH) + 2 * 2048)     // 2*128*8 floats
#define SMEM_TOTAL (RED_OFF + 8192)

// ---------------- device scratch ----------------
__device__ __align__(16) __half g_a  [NTOK * 128];   // queries  [qr|qi] K-major
__device__ __align__(16) __half g_bre[NTOK * 128];   // keys [kr|ki]
__device__ __align__(16) __half g_bim[NTOK * 128];   // keys [ki|-kr]
__device__ __align__(16) float  g_v  [NTOK * 8];     // <Z_q>, padded to 8
__device__ float  g_part[(size_t)NSPLIT * NTOK * 8];
__device__ float2 g_trig[3 * 24];                    // per-set param sincos

// ---------------- PTX helpers (all baseline compute_103) ----------------
__device__ __forceinline__ uint32_t smem_u32(const void* p) {
    uint32_t a;
    asm("{ .reg .u64 t; cvta.to.shared.u64 t, %1; cvt.u32.u64 %0, t; }" : "=r"(a) : "l"(p));
    return a;
}
__device__ __forceinline__ void cp16(uint32_t s, const void* g) {
    asm volatile("cp.async.cg.shared.global [%0], [%1], 16;" :: "r"(s), "l"(g));
}
__device__ __forceinline__ void cp_commit() { asm volatile("cp.async.commit_group;"); }
__device__ __forceinline__ void cp_wait()   { asm volatile("cp.async.wait_group 0;" ::: "memory"); }

__device__ __forceinline__ void ldsm_x4(uint32_t& r0, uint32_t& r1, uint32_t& r2, uint32_t& r3, uint32_t a) {
    asm volatile("ldmatrix.sync.aligned.m8n8.x4.shared.b16 {%0,%1,%2,%3}, [%4];"
                 : "=r"(r0), "=r"(r1), "=r"(r2), "=r"(r3) : "r"(a));
}
// NON-trans: smem key-rows with K contiguous are already col-major KxN,
// thread r -> key row r, gives the exact m16n8k16 B fragment.
__device__ __forceinline__ void ldsm_x2(uint32_t& r0, uint32_t& r1, uint32_t a) {
    asm volatile("ldmatrix.sync.aligned.m8n8.x2.shared.b16 {%0,%1}, [%2];"
                 : "=r"(r0), "=r"(r1) : "r"(a));
}
__device__ __forceinline__ void mma16816(float* c, const uint32_t* a, const uint32_t* b) {
    asm volatile("mma.sync.aligned.m16n8k16.row.col.f32.f16.f16.f32 "
                 "{%0,%1,%2,%3}, {%4,%5,%6,%7}, {%8,%9}, {%0,%1,%2,%3};"
                 : "+f"(c[0]), "+f"(c[1]), "+f"(c[2]), "+f"(c[3])
                 : "r"(a[0]), "r"(a[1]), "r"(a[2]), "r"(a[3]), "r"(b[0]), "r"(b[1]));
}

// ---------------- quantum state prep ----------------
__device__ __forceinline__ void ry_sc(float s, float c, int q, int lane,
        float& a0x, float& a0y, float& a1x, float& a1y)
{
    if (q == 5) {
        float n0x = c*a0x - s*a1x, n0y = c*a0y - s*a1y;
        float n1x = s*a0x + c*a1x, n1y = s*a0y + c*a1y;
        a0x = n0x; a0y = n0y; a1x = n1x; a1y = n1y;
    } else {
        int sh = 4 - q, m = 1 << sh;
        float o0x = __shfl_xor_sync(0xffffffffu, a0x, m);
        float o0y = __shfl_xor_sync(0xffffffffu, a0y, m);
        float o1x = __shfl_xor_sync(0xffffffffu, a1x, m);
        float o1y = __shfl_xor_sync(0xffffffffu, a1y, m);
        float sg = ((lane >> sh) & 1) ? s : -s;
        a0x = c*a0x + sg*o0x; a0y = c*a0y + sg*o0y;
        a1x = c*a1x + sg*o1x; a1y = c*a1y + sg*o1y;
    }
}

__device__ __forceinline__ void rz_sc(float s, float c, int q, int lane,
        float& a0x, float& a0y, float& a1x, float& a1y)
{
    if (q == 5) {
        float n0x = a0x*c + a0y*s, n0y = a0y*c - a0x*s;
        float n1x = a1x*c - a1y*s, n1y = a1y*c + a1x*s;
        a0x = n0x; a0y = n0y; a1x = n1x; a1y = n1y;
    } else {
        float t = ((lane >> (4 - q)) & 1) ? s : -s;
        float n0x = a0x*c - a0y*t, n0y = a0y*c + a0x*t;
        float n1x = a1x*c - a1y*t, n1y = a1y*c + a1x*t;
        a0x = n0x; a0y = n0y; a1x = n1x; a1y = n1y;
    }
}

__device__ __forceinline__ void cnot_ll(int csh, int tmask, int lane,
        float& a0x, float& a0y, float& a1x, float& a1y)
{
    float o0x = __shfl_xor_sync(0xffffffffu, a0x, tmask);
    float o0y = __shfl_xor_sync(0xffffffffu, a0y, tmask);
    float o1x = __shfl_xor_sync(0xffffffffu, a1x, tmask);
    float o1y = __shfl_xor_sync(0xffffffffu, a1y, tmask);
    if ((lane >> csh) & 1) { a0x = o0x; a0y = o0y; a1x = o1x; a1y = o1y; }
}

__global__ void trig_kernel(const float* __restrict__ pq,
                            const float* __restrict__ pk,
                            const float* __restrict__ pv)
{
    int i = threadIdx.x;
    if (i < 72) {
        int set = i / 24, r = i % 24;
        const float* p = (set == 0) ? pq : (set == 1) ? pk : pv;
        float s, c;
        sincosf(0.5f * p[r], &s, &c);
        g_trig[i] = make_float2(s, c);
    }
}

__global__ void prep_kernel(const float* __restrict__ x)
{
    int gw   = (blockIdx.x * blockDim.x + threadIdx.x) >> 5;
    int lane = threadIdx.x & 31;
    int set  = gw >> 13;            // 0=Q, 1=K, 2=V
    int tok  = gw & (NTOK - 1);
    const float2* trig = g_trig + set * 24;

    float a0x = (lane == 0) ? 1.f : 0.f, a0y = 0.f, a1x = 0.f, a1y = 0.f;

    #pragma unroll
    for (int q = 0; q < 6; q++) {
        float s, c;
        sincosf(0.5f * x[tok * 6 + q], &s, &c);
        ry_sc(s, c, q, lane, a0x, a0y, a1x, a1y);
    }

    #pragma unroll
    for (int l = 0; l < 2; l++) {
        #pragma unroll
        for (int q = 0; q < 6; q++) {
            float2 ty = trig[(l * 6 + q) * 2 + 0];
            ry_sc(ty.x, ty.y, q, lane, a0x, a0y, a1x, a1y);
            float2 tz = trig[(l * 6 + q) * 2 + 1];
            rz_sc(tz.x, tz.y, q, lane, a0x, a0y, a1x, a1y);
        }
        cnot_ll(4, 8, lane, a0x, a0y, a1x, a1y);
        cnot_ll(3, 4, lane, a0x, a0y, a1x, a1y);
        cnot_ll(2, 2, lane, a0x, a0y, a1x, a1y);
        cnot_ll(1, 1, lane, a0x, a0y, a1x, a1y);
        if (lane & 1) {
            float t;
            t = a0x; a0x = a1x; a1x = t;
            t = a0y; a0y = a1y; a1y = t;
        }
        a1x = __shfl_xor_sync(0xffffffffu, a1x, 16);
        a1y = __shfl_xor_sync(0xffffffffu, a1y, 16);
    }

    if (set == 0) {
        __half2* A = (__half2*)g_a + tok * 64;
        A[lane]      = __floats2half2_rn(a0x, a1x);
        A[32 + lane] = __floats2half2_rn(a0y, a1y);
    } else if (set == 1) {
        __half2* R = (__half2*)g_bre + tok * 64;
        R[lane]      = __floats2half2_rn(a0x, a1x);
        R[32 + lane] = __floats2half2_rn(a0y, a1y);
        __half2* I = (__half2*)g_bim + tok * 64;   // w = [ki | -kr]
        I[lane]      = __floats2half2_rn(a0y, a1y);
        I[32 + lane] = __floats2half2_rn(-a0x, -a1x);
    } else {
        float p0 = a0x*a0x + a0y*a0y;
        float p1 = a1x*a1x + a1y*a1y;
        int d0 = lane * 2, d1 = lane * 2 + 1;
        #pragma unroll
        for (int q = 0; q < 6; q++) {
            float s0 = ((d0 >> (5 - q)) & 1) ? -1.f : 1.f;
            float s1 = ((d1 >> (5 - q)) & 1) ? -1.f : 1.f;
            float z = s0 * p0 + s1 * p1;
            #pragma unroll
            for (int o = 16; o; o >>= 1) z += __shfl_xor_sync(0xffffffffu, z, o);
            if (lane == 0) g_v[tok * 8 + q] = z;
        }
    }
}

// ---------------- fused attention (HMMA + register epilogue) ----------------
extern __shared__ char smx[];

// issue async loads of one 64-key chunk (bre + bim + V) into buffer p
__device__ __forceinline__ void issue_chunk(uint32_t smb, int p, int kb, int tid)
{
    // 2176 16B chunks: 1024 bre, 1024 bim, 128 V
    #pragma unroll
    for (int it = 0; it < 9; it++) {
        int i = it * 256 + tid;
        if (i < 1024) {
            int row = i >> 4, ch = i & 15;
            cp16(smb + BRE_OFF(p) + row * PITCH + ch * 16,
                 g_bre + (size_t)(kb + row) * 128 + ch * 8);
        } else if (i < 2048) {
            int j = i - 1024, row = j >> 4, ch = j & 15;
            cp16(smb + BIM_OFF(p) + row * PITCH + ch * 16,
                 g_bim + (size_t)(kb + row) * 128 + ch * 8);
        } else if (i < 2176) {
            int j = i - 2048;
            cp16(smb + V_OFF(p) + j * 16, (const char*)g_v + (size_t)kb * 32 + j * 16);
        }
    }
    cp_commit();
}

__global__ void __launch_bounds__(256, 1) attn_kernel()
{
    char* sm = smx;
    uint32_t smb = smem_u32(sm);
    int tid  = threadIdx.x;
    int wid  = tid >> 5, lane = tid & 31;
    int wrow = wid & 3, wcol = wid >> 2;      // warp grid 4x2
    int mwarp = wrow * 32;                    // rows per warp: 32
    int nwarp = wcol * 32;                    // cols per warp: 32
    int qbase  = blockIdx.x * 128;
    int kbase0 = blockIdx.y * KEYS_PER_SPLIT;

    // prologue: A tile + chunk 0 via cp.async
    #pragma unroll
    for (int e = 0; e < 8; e++) {
        int i = e * 256 + tid;
        int row = i >> 4, ch = i & 15;
        cp16(smb + A_OFF + row * PITCH + ch * 16,
             g_a + (size_t)(qbase + row) * 128 + ch * 8);
    }
    issue_chunk(smb, 0, kbase0, tid);
    cp_wait();
    __syncthreads();

    // A fragments, resident in registers for the whole CTA
    uint32_t afr[2][8][4];
    {
        int rowa = mwarp + (lane & 15);
        int offa = (lane >> 4) * 16;
        #pragma unroll
        for (int rt = 0; rt < 2; rt++)
            #pragma unroll
            for (int kt = 0; kt < 8; kt++)
                ldsm_x4(afr[rt][kt][0], afr[rt][kt][1], afr[rt][kt][2], afr[rt][kt][3],
                        smb + A_OFF + (rowa + rt * 16) * PITCH + kt * 32 + offa);
    }

    float den4[4] = {0.f, 0.f, 0.f, 0.f};
    float num4[4][6];
    #pragma unroll
    for (int d = 0; d < 4; d++)
        #pragma unroll
        for (int c = 0; c < 6; c++) num4[d][c] = 0.f;

    int rowb = nwarp + (lane & 7);
    int offb = ((lane >> 3) & 1) * 16;

    for (int c = 0; c < CHUNKS; c++) {
        int p = c & 1;
        if (c + 1 < CHUNKS) issue_chunk(smb, 1 - p, kbase0 + (c + 1) * BN, tid);

        float RE[2][4][4], IM[2][4][4];
        #pragma unroll
        for (int rt = 0; rt < 2; rt++)
            #pragma unroll
            for (int ct = 0; ct < 4; ct++)
                #pragma unroll
                for (int e = 0; e < 4; e++) { RE[rt][ct][e] = 0.f; IM[rt][ct][e] = 0.f; }

        #pragma unroll
        for (int kt = 0; kt < 8; kt++) {
            uint32_t bre[4][2], bim[4][2];
            #pragma unroll
            for (int ct = 0; ct < 4; ct++) {
                uint32_t ra = smb + BRE_OFF(p) + (rowb + ct * 8) * PITCH + kt * 32 + offb;
                uint32_t ia = smb + BIM_OFF(p) + (rowb + ct * 8) * PITCH + kt * 32 + offb;
                ldsm_x2(bre[ct][0], bre[ct][1], ra);
                ldsm_x2(bim[ct][0], bim[ct][1], ia);
            }
            #pragma unroll
            for (int ct = 0; ct < 4; ct++)
                #pragma unroll
                for (int rt = 0; rt < 2; rt++) {
                    mma16816(RE[rt][ct], afr[rt][kt], bre[ct]);
                    mma16816(IM[rt][ct], afr[rt][kt], bim[ct]);
                }
        }

        // epilogue on register accumulators
        #pragma unroll
        for (int ct = 0; ct < 4; ct++) {
            int c0 = nwarp + ct * 8 + 2 * (lane & 3);
            const float* v0 = (const float*)(sm + V_OFF(p) + c0 * 32);
            float4 v0a = *(const float4*)v0;
            float2 v0b = *(const float2*)(v0 + 4);
            float4 v1a = *(const float4*)(v0 + 8);
            float2 v1b = *(const float2*)(v0 + 12);
            #pragma unroll
            for (int rt = 0; rt < 2; rt++)
                #pragma unroll
                for (int e = 0; e < 4; e++) {
                    float rr = RE[rt][ct][e], ii = IM[rt][ct][e];
                    float pe = __expf(fmaf(rr, rr, ii * ii));   // logit in [0,1]
                    int d = (e >> 1) + 2 * rt;
                    den4[d] += pe;
                    if (e & 1) {
                        num4[d][0] = fmaf(pe, v1a.x, num4[d][0]);
                        num4[d][1] = fmaf(pe, v1a.y, num4[d][1]);
                        num4[d][2] = fmaf(pe, v1a.z, num4[d][2]);
                        num4[d][3] = fmaf(pe, v1a.w, num4[d][3]);
                        num4[d][4] = fmaf(pe, v1b.x, num4[d][4]);
                        num4[d][5] = fmaf(pe, v1b.y, num4[d][5]);
                    } else {
                        num4[d][0] = fmaf(pe, v0a.x, num4[d][0]);
                        num4[d][1] = fmaf(pe, v0a.y, num4[d][1]);
                        num4[d][2] = fmaf(pe, v0a.z, num4[d][2]);
                        num4[d][3] = fmaf(pe, v0a.w, num4[d][3]);
                        num4[d][4] = fmaf(pe, v0b.x, num4[d][4]);
                        num4[d][5] = fmaf(pe, v0b.y, num4[d][5]);
                    }
                }
        }

        cp_wait();
        __syncthreads();
    }

    // reduce across the 4 lanes of each row-group (lane&3)
    #pragma unroll
    for (int off = 1; off <= 2; off <<= 1) {
        #pragma unroll
        for (int d = 0; d < 4; d++) {
            den4[d] += __shfl_xor_sync(0xffffffffu, den4[d], off);
            #pragma unroll
            for (int c = 0; c < 6; c++)
                num4[d][c] += __shfl_xor_sync(0xffffffffu, num4[d][c], off);
        }
    }
    if ((lane & 3) == 0) {
        #pragma unroll
        for (int d = 0; d < 4; d++) {
            int row = mwarp + (lane >> 2) + 8 * (d & 1) + 16 * (d >> 1);
            float* rp = (float*)(sm + RED_OFF) + (wcol * 128 + row) * 8;
            #pragma unroll
            for (int c = 0; c < 6; c++) rp[c] = num4[d][c];
            rp[6] = den4[d];
        }
    }
    __syncthreads();
    if (tid < 128) {
        const float* a = (const float*)(sm + RED_OFF) + tid * 8;
        const float* b = a + 128 * 8;
        float* out = g_part + ((size_t)blockIdx.y * NTOK + qbase + tid) * 8;
        #pragma unroll
        for (int c = 0; c < 7; c++) out[c] = a[c] + b[c];
    }
}

__global__ void finalize_kernel(float* __restrict__ out)
{
    int i = blockIdx.x * blockDim.x + threadIdx.x;
    float a0 = 0.f, a1 = 0.f, a2 = 0.f, a3 = 0.f, a4 = 0.f, a5 = 0.f, dn = 0.f;
    #pragma unroll
    for (int s = 0; s < NSPLIT; s++) {
        const float* p = g_part + ((size_t)s * NTOK + i) * 8;
        a0 += p[0]; a1 += p[1]; a2 += p[2];
        a3 += p[3]; a4 += p[4]; a5 += p[5];
        dn += p[6];
    }
    float inv = 1.0f / dn;
    out[i * 6 + 0] = a0 * inv;
    out[i * 6 + 1] = a1 * inv;
    out[i * 6 + 2] = a2 * inv;
    out[i * 6 + 3] = a3 * inv;
    out[i * 6 + 4] = a4 * inv;
    out[i * 6 + 5] = a5 * inv;
}

extern "C" void kernel_launch(void* const* d_in, const int* in_sizes, int n_in,
                              void* d_out, int out_size)
{
    const float* x  = (const float*)d_in[0];
    const float* pq = (const float*)d_in[1];
    const float* pk = (const float*)d_in[2];
    const float* pv = (const float*)d_in[3];

    trig_kernel<<<1, 128>>>(pq, pk, pv);
    prep_kernel<<<(3 * NTOK) / 8, 256>>>(x);

    cudaFuncSetAttribute(attn_kernel, cudaFuncAttributeMaxDynamicSharedMemorySize, SMEM_TOTAL);
    attn_kernel<<<dim3(NTOK / 128, NSPLIT), 256, SMEM_TOTAL>>>();

    finalize_kernel<<<NTOK / 256, 256>>>((float*)d_out);
}

// round 7
// speedup vs baseline: 6.4207x; 1.4468x over previous
#include <cuda_runtime.h>
#include <cuda_fp16.h>
#include <cstdint>

typedef unsigned long long u64;

#define NTOK 8192
#define NSPLIT 2
#define KEYS_PER_SPLIT (NTOK / NSPLIT)   // 4096
#define BN 64                            // keys per chunk
#define CHUNKS (KEYS_PER_SPLIT / BN)     // 64
#define PITCH 144                        // 128B row + 16B pad (odd 16B stride -> conflict-free)

// ---- smem layout (bytes) ----
#define A_OFF    0                       // 128 rows x 128B (phi, fp16 K=64)
#define B_OFF0   18432
#define B_OFF1   36864                   // per buf: 128 col-rows x 128B (psi re/im interleaved)
#define V_OFF(p) (55296 + (p) * 2048)    // 64 keys x 8 floats
#define RED_OFF  59392                   // 2 * 128 * 8 floats
#define SMEM_TOTAL 67584

// ---------------- device scratch ----------------
__device__ __align__(16) __half g_a[NTOK * 64];    // phi_i (real, K=64)
__device__ __align__(16) __half g_b[NTOK * 128];   // rows 2j: Re(psi_j), 2j+1: Im(psi_j)
__device__ __align__(16) float  g_v[NTOK * 8];     // <Z_q>, padded to 8
__device__ float  g_part[(size_t)NSPLIT * NTOK * 8];
__device__ float2 g_trig[3 * 24];                  // per-set param sincos

// ---------------- PTX helpers ----------------
__device__ __forceinline__ uint32_t smem_u32(const void* p) {
    uint32_t a;
    asm("{ .reg .u64 t; cvta.to.shared.u64 t, %1; cvt.u32.u64 %0, t; }" : "=r"(a) : "l"(p));
    return a;
}
__device__ __forceinline__ void cp16(uint32_t s, const void* g) {
    asm volatile("cp.async.cg.shared.global [%0], [%1], 16;" :: "r"(s), "l"(g));
}
__device__ __forceinline__ void cp_commit() { asm volatile("cp.async.commit_group;"); }
__device__ __forceinline__ void cp_wait()   { asm volatile("cp.async.wait_group 0;" ::: "memory"); }

__device__ __forceinline__ void ldsm_x4(uint32_t& r0, uint32_t& r1, uint32_t& r2, uint32_t& r3, uint32_t a) {
    asm volatile("ldmatrix.sync.aligned.m8n8.x4.shared.b16 {%0,%1,%2,%3}, [%4];"
                 : "=r"(r0), "=r"(r1), "=r"(r2), "=r"(r3) : "r"(a));
}
__device__ __forceinline__ void mma16816(float* c, const uint32_t* a, const uint32_t* b) {
    asm volatile("mma.sync.aligned.m16n8k16.row.col.f32.f16.f16.f32 "
                 "{%0,%1,%2,%3}, {%4,%5,%6,%7}, {%8,%9}, {%0,%1,%2,%3};"
                 : "+f"(c[0]), "+f"(c[1]), "+f"(c[2]), "+f"(c[3])
                 : "r"(a[0]), "r"(a[1]), "r"(a[2]), "r"(a[3]), "r"(b[0]), "r"(b[1]));
}

// ---------------- quantum gates (warp-distributed 64-amp state) ----------------
__device__ __forceinline__ void ry_sc(float s, float c, int q, int lane,
        float& a0x, float& a0y, float& a1x, float& a1y)
{
    if (q == 5) {
        float n0x = c*a0x - s*a1x, n0y = c*a0y - s*a1y;
        float n1x = s*a0x + c*a1x, n1y = s*a0y + c*a1y;
        a0x = n0x; a0y = n0y; a1x = n1x; a1y = n1y;
    } else {
        int sh = 4 - q, m = 1 << sh;
        float o0x = __shfl_xor_sync(0xffffffffu, a0x, m);
        float o0y = __shfl_xor_sync(0xffffffffu, a0y, m);
        float o1x = __shfl_xor_sync(0xffffffffu, a1x, m);
        float o1y = __shfl_xor_sync(0xffffffffu, a1y, m);
        float sg = ((lane >> sh) & 1) ? s : -s;
        a0x = c*a0x + sg*o0x; a0y = c*a0y + sg*o0y;
        a1x = c*a1x + sg*o1x; a1y = c*a1y + sg*o1y;
    }
}

__device__ __forceinline__ void rz_sc(float s, float c, int q, int lane,
        float& a0x, float& a0y, float& a1x, float& a1y)
{
    if (q == 5) {
        float n0x = a0x*c + a0y*s, n0y = a0y*c - a0x*s;
        float n1x = a1x*c - a1y*s, n1y = a1y*c + a1x*s;
        a0x = n0x; a0y = n0y; a1x = n1x; a1y = n1y;
    } else {
        float t = ((lane >> (4 - q)) & 1) ? s : -s;
        float n0x = a0x*c - a0y*t, n0y = a0y*c + a0x*t;
        float n1x = a1x*c - a1y*t, n1y = a1y*c + a1x*t;
        a0x = n0x; a0y = n0y; a1x = n1x; a1y = n1y;
    }
}

__device__ __forceinline__ void cnot_ll(int csh, int tmask, int lane,
        float& a0x, float& a0y, float& a1x, float& a1y)
{
    float o0x = __shfl_xor_sync(0xffffffffu, a0x, tmask);
    float o0y = __shfl_xor_sync(0xffffffffu, a0y, tmask);
    float o1x = __shfl_xor_sync(0xffffffffu, a1x, tmask);
    float o1y = __shfl_xor_sync(0xffffffffu, a1y, tmask);
    if ((lane >> csh) & 1) { a0x = o0x; a0y = o0y; a1x = o1x; a1y = o1y; }
}

// forward PQC: for l: {RY,RZ per q}, then ring (0,1)..(5,0)
__device__ __forceinline__ void pqc_fwd(const float2* trig, int lane,
        float& a0x, float& a0y, float& a1x, float& a1y)
{
    #pragma unroll
    for (int l = 0; l < 2; l++) {
        #pragma unroll
        for (int q = 0; q < 6; q++) {
            float2 ty = trig[(l * 6 + q) * 2 + 0];
            ry_sc(ty.x, ty.y, q, lane, a0x, a0y, a1x, a1y);
            float2 tz = trig[(l * 6 + q) * 2 + 1];
            rz_sc(tz.x, tz.y, q, lane, a0x, a0y, a1x, a1y);
        }
        cnot_ll(4, 8, lane, a0x, a0y, a1x, a1y);   // (0,1)
        cnot_ll(3, 4, lane, a0x, a0y, a1x, a1y);   // (1,2)
        cnot_ll(2, 2, lane, a0x, a0y, a1x, a1y);   // (2,3)
        cnot_ll(1, 1, lane, a0x, a0y, a1x, a1y);   // (3,4)
        if (lane & 1) {                            // (4,5)
            float t;
            t = a0x; a0x = a1x; a1x = t;
            t = a0y; a0y = a1y; a1y = t;
        }
        a1x = __shfl_xor_sync(0xffffffffu, a1x, 16);   // (5,0)
        a1y = __shfl_xor_sync(0xffffffffu, a1y, 16);
    }
}

// inverse PQC (P^H): layers reversed; per layer: reverse ring, then RZ(-),RY(-) per q
__device__ __forceinline__ void pqc_inv(const float2* trig, int lane,
        float& a0x, float& a0y, float& a1x, float& a1y)
{
    #pragma unroll
    for (int l = 1; l >= 0; l--) {
        a1x = __shfl_xor_sync(0xffffffffu, a1x, 16);   // (5,0)
        a1y = __shfl_xor_sync(0xffffffffu, a1y, 16);
        if (lane & 1) {                                 // (4,5)
            float t;
            t = a0x; a0x = a1x; a1x = t;
            t = a0y; a0y = a1y; a1y = t;
        }
        cnot_ll(1, 1, lane, a0x, a0y, a1x, a1y);        // (3,4)
        cnot_ll(2, 2, lane, a0x, a0y, a1x, a1y);        // (2,3)
        cnot_ll(3, 4, lane, a0x, a0y, a1x, a1y);        // (1,2)
        cnot_ll(4, 8, lane, a0x, a0y, a1x, a1y);        // (0,1)
        #pragma unroll
        for (int q = 0; q < 6; q++) {
            float2 tz = trig[(l * 6 + q) * 2 + 1];
            rz_sc(-tz.x, tz.y, q, lane, a0x, a0y, a1x, a1y);
            float2 ty = trig[(l * 6 + q) * 2 + 0];
            ry_sc(-ty.x, ty.y, q, lane, a0x, a0y, a1x, a1y);
        }
    }
}

__global__ void trig_kernel(const float* __restrict__ pq,
                            const float* __restrict__ pk,
                            const float* __restrict__ pv)
{
    int i = threadIdx.x;
    if (i < 72) {
        int set = i / 24, r = i % 24;
        const float* p = (set == 0) ? pq : (set == 1) ? pk : pv;
        float s, c;
        sincosf(0.5f * p[r], &s, &c);
        g_trig[i] = make_float2(s, c);
    }
}

__global__ void prep_kernel(const float* __restrict__ x)
{
    int gw   = (blockIdx.x * blockDim.x + threadIdx.x) >> 5;
    int lane = threadIdx.x & 31;
    int set  = gw >> 13;            // 0=Q(phi), 1=K(psi), 2=V
    int tok  = gw & (NTOK - 1);

    float a0x = (lane == 0) ? 1.f : 0.f, a0y = 0.f, a1x = 0.f, a1y = 0.f;

    // RY angle embedding (all sets) — result real for set 0
    #pragma unroll
    for (int q = 0; q < 6; q++) {
        float s, c;
        sincosf(0.5f * x[tok * 6 + q], &s, &c);
        ry_sc(s, c, q, lane, a0x, a0y, a1x, a1y);
    }

    if (set == 0) {
        // phi_i: real embedding state only
        ((__half2*)g_a)[tok * 32 + lane] = __floats2half2_rn(a0x, a1x);
    } else if (set == 1) {
        // psi_j = P_q^H (P_k E(x_j)|0>)
        pqc_fwd(g_trig + 24, lane, a0x, a0y, a1x, a1y);   // K-PQC
        pqc_inv(g_trig + 0,  lane, a0x, a0y, a1x, a1y);   // inverse Q-PQC
        ((__half2*)g_b)[(tok * 2 + 0) * 32 + lane] = __floats2half2_rn(a0x, a1x);  // Re
        ((__half2*)g_b)[(tok * 2 + 1) * 32 + lane] = __floats2half2_rn(a0y, a1y);  // Im
    } else {
        pqc_fwd(g_trig + 48, lane, a0x, a0y, a1x, a1y);   // V-PQC
        float p0 = a0x*a0x + a0y*a0y;
        float p1 = a1x*a1x + a1y*a1y;
        int d0 = lane * 2, d1 = lane * 2 + 1;
        #pragma unroll
        for (int q = 0; q < 6; q++) {
            float s0 = ((d0 >> (5 - q)) & 1) ? -1.f : 1.f;
            float s1 = ((d1 >> (5 - q)) & 1) ? -1.f : 1.f;
            float z = s0 * p0 + s1 * p1;
            #pragma unroll
            for (int o = 16; o; o >>= 1) z += __shfl_xor_sync(0xffffffffu, z, o);
            if (lane == 0) g_v[tok * 8 + q] = z;
        }
    }
}

// ---------------- fused attention ----------------
extern __shared__ char smx[];

// async load one 64-key chunk: 128 psi col-rows (16KB) + 64 V rows (2KB)
__device__ __forceinline__ void issue_chunk(uint32_t smb, uint32_t boff, int p, int kb, int tid)
{
    #pragma unroll
    for (int it = 0; it < 5; it++) {
        int i = it * 256 + tid;
        if (i < 1024) {
            int row = i >> 3, ch = i & 7;
            cp16(smb + boff + row * PITCH + ch * 16,
                 g_b + (size_t)(kb * 2 + row) * 64 + ch * 8);
        } else if (i < 1152) {
            int j = i - 1024;
            cp16(smb + V_OFF(p) + j * 16, (const char*)g_v + (size_t)kb * 32 + j * 16);
        }
    }
    cp_commit();
}

__global__ void __launch_bounds__(256, 1) attn_kernel()
{
    char* sm = smx;
    uint32_t smb = smem_u32(sm);
    int tid  = threadIdx.x;
    int wid  = tid >> 5, lane = tid & 31;
    int wrow = wid & 3, wcol = wid >> 2;      // warp grid 4x2
    int mwarp = wrow * 32;                    // 32 query rows per warp
    int nbase = wcol * 64;                    // 64 B-cols (=32 keys) per warp
    int qbase  = blockIdx.x * 128;
    int kbase0 = blockIdx.y * KEYS_PER_SPLIT;

    // prologue: A (phi) tile + chunk 0
    #pragma unroll
    for (int e = 0; e < 4; e++) {
        int i = e * 256 + tid;
        int row = i >> 3, ch = i & 7;
        cp16(smb + A_OFF + row * PITCH + ch * 16,
             g_a + (size_t)(qbase + row) * 64 + ch * 8);
    }
    issue_chunk(smb, B_OFF0, 0, kbase0, tid);
    cp_wait();
    __syncthreads();

    // A fragments resident: K=64 -> 4 kt
    uint32_t afr[2][4][4];
    {
        int rowa = mwarp + (lane & 15);
        int offa = (lane >> 4) * 16;
        #pragma unroll
        for (int rt = 0; rt < 2; rt++)
            #pragma unroll
            for (int kt = 0; kt < 4; kt++)
                ldsm_x4(afr[rt][kt][0], afr[rt][kt][1], afr[rt][kt][2], afr[rt][kt][3],
                        smb + A_OFF + (rowa + rt * 16) * PITCH + kt * 32 + offa);
    }

    float den4[4] = {0.f, 0.f, 0.f, 0.f};
    float num4[4][6];
    #pragma unroll
    for (int d = 0; d < 4; d++)
        #pragma unroll
        for (int c = 0; c < 6; c++) num4[d][c] = 0.f;

    // B ldmatrix x4 address components (matrices: {ct,k0-7},{ct,k8-15},{ct+1,k0-7},{ct+1,k8-15})
    int brow_l = nbase + (lane >> 4) * 8 + (lane & 7);
    int boffk  = ((lane >> 3) & 1) * 16;

    for (int c = 0; c < CHUNKS; c++) {
        int p = c & 1;
        uint32_t boff  = p ? B_OFF1 : B_OFF0;
        uint32_t boff2 = p ? B_OFF0 : B_OFF1;
        if (c + 1 < CHUNKS) issue_chunk(smb, boff2, 1 - p, kbase0 + (c + 1) * BN, tid);

        float acc[2][8][4];
        #pragma unroll
        for (int rt = 0; rt < 2; rt++)
            #pragma unroll
            for (int ct = 0; ct < 8; ct++)
                #pragma unroll
                for (int e = 0; e < 4; e++) acc[rt][ct][e] = 0.f;

        #pragma unroll
        for (int kt = 0; kt < 4; kt++) {
            uint32_t bfr[8][2];
            #pragma unroll
            for (int cp2 = 0; cp2 < 4; cp2++) {
                uint32_t r0, r1, r2, r3;
                ldsm_x4(r0, r1, r2, r3,
                        smb + boff + (brow_l + cp2 * 16) * PITCH + kt * 32 + boffk);
                bfr[2*cp2][0] = r0; bfr[2*cp2][1] = r1;
                bfr[2*cp2+1][0] = r2; bfr[2*cp2+1][1] = r3;
            }
            #pragma unroll
            for (int ct = 0; ct < 8; ct++)
                #pragma unroll
                for (int rt = 0; rt < 2; rt++)
                    mma16816(acc[rt][ct], afr[rt][kt], bfr[ct]);
        }

        // epilogue: thread holds (Re,Im) adjacent (cols 2j, 2j+1)
        #pragma unroll
        for (int ct = 0; ct < 8; ct++) {
            int jl = wcol * 32 + ct * 4 + (lane & 3);
            const float* vv = (const float*)(sm + V_OFF(p) + jl * 32);
            float4 va = *(const float4*)vv;
            float2 vb = *(const float2*)(vv + 4);
            #pragma unroll
            for (int rt = 0; rt < 2; rt++)
                #pragma unroll
                for (int h = 0; h < 2; h++) {
                    float rr = acc[rt][ct][2*h], ii = acc[rt][ct][2*h + 1];
                    float pe = __expf(fmaf(rr, rr, ii * ii));   // logit in [0,1]
                    int d = 2 * rt + h;
                    den4[d] += pe;
                    num4[d][0] = fmaf(pe, va.x, num4[d][0]);
                    num4[d][1] = fmaf(pe, va.y, num4[d][1]);
                    num4[d][2] = fmaf(pe, va.z, num4[d][2]);
                    num4[d][3] = fmaf(pe, va.w, num4[d][3]);
                    num4[d][4] = fmaf(pe, vb.x, num4[d][4]);
                    num4[d][5] = fmaf(pe, vb.y, num4[d][5]);
                }
        }

        cp_wait();
        __syncthreads();
    }

    // reduce over lane&3 (4 lanes share each row)
    #pragma unroll
    for (int off = 1; off <= 2; off <<= 1) {
        #pragma unroll
        for (int d = 0; d < 4; d++) {
            den4[d] += __shfl_xor_sync(0xffffffffu, den4[d], off);
            #pragma unroll
            for (int c = 0; c < 6; c++)
                num4[d][c] += __shfl_xor_sync(0xffffffffu, num4[d][c], off);
        }
    }
    if ((lane & 3) == 0) {
        #pragma unroll
        for (int d = 0; d < 4; d++) {
            int row = mwarp + (lane >> 2) + 8 * (d & 1) + 16 * (d >> 1);
            float* rp = (float*)(sm + RED_OFF) + (wcol * 128 + row) * 8;
            #pragma unroll
            for (int c = 0; c < 6; c++) rp[c] = num4[d][c];
            rp[6] = den4[d];
        }
    }
    __syncthreads();
    if (tid < 128) {
        const float* a = (const float*)(sm + RED_OFF) + tid * 8;
        const float* b = a + 128 * 8;
        float* out = g_part + ((size_t)blockIdx.y * NTOK + qbase + tid) * 8;
        #pragma unroll
        for (int c = 0; c < 7; c++) out[c] = a[c] + b[c];
    }
}

__global__ void finalize_kernel(float* __restrict__ out)
{
    int i = blockIdx.x * blockDim.x + threadIdx.x;
    float a0 = 0.f, a1 = 0.f, a2 = 0.f, a3 = 0.f, a4 = 0.f, a5 = 0.f, dn = 0.f;
    #pragma unroll
    for (int s = 0; s < NSPLIT; s++) {
        const float* p = g_part + ((size_t)s * NTOK + i) * 8;
        a0 += p[0]; a1 += p[1]; a2 += p[2];
        a3 += p[3]; a4 += p[4]; a5 += p[5];
        dn += p[6];
    }
    float inv = 1.0f / dn;
    out[i * 6 + 0] = a0 * inv;
    out[i * 6 + 1] = a1 * inv;
    out[i * 6 + 2] = a2 * inv;
    out[i * 6 + 3] = a3 * inv;
    out[i * 6 + 4] = a4 * inv;
    out[i * 6 + 5] = a5 * inv;
}

extern "C" void kernel_launch(void* const* d_in, const int* in_sizes, int n_in,
                              void* d_out, int out_size)
{
    const float* x  = (const float*)d_in[0];
    const float* pq = (const float*)d_in[1];
    const float* pk = (const float*)d_in[2];
    const float* pv = (const float*)d_in[3];

    trig_kernel<<<1, 128>>>(pq, pk, pv);
    prep_kernel<<<(3 * NTOK) / 8, 256>>>(x);

    cudaFuncSetAttribute(attn_kernel, cudaFuncAttributeMaxDynamicSharedMemorySize, SMEM_TOTAL);
    attn_kernel<<<dim3(NTOK / 128, NSPLIT), 256, SMEM_TOTAL>>>();

    finalize_kernel<<<NTOK / 256, 256>>>((float*)d_out);
}

// round 10
// speedup vs baseline: 7.2573x; 1.1303x over previous
#include <cuda_runtime.h>
#include <cuda_fp16.h>
#include <cstdint>

typedef unsigned long long u64;

#define NTOK 8192
#define GCTAS 148
#define NUNITS 8192                      // 64 qtiles * 128 chunks

// ---- smem layout (bytes) ----
#define A_OFF    0                       // 128 rows x 128B phi (pitch 144)
#define B_OFF0   18432
#define B_OFF1   36864                   // psi tiles, 128 rows x 128B (pitch 144)
#define VT_OFF(p) (55296 + (p) * 1152)   // 8 rows x 128B (pitch 144)
#define P_OFF    57600                   // 8 warps x (32 rows x 80B) = 20480
#define RED_OFF  78080                   // 128 x 8 floats
#define SMEM_TOTAL 82176

// ---------------- device scratch ----------------
__device__ __align__(16) __half g_a [NTOK * 64];    // phi_i (real, K=64)
__device__ __align__(16) __half g_b [NTOK * 128];   // rows 2j: Re(psi_j), 2j+1: Im(psi_j)
__device__ __align__(16) __half g_vt[8 * NTOK];     // rows 0-5: <Z_q>, row6: ones, row7: 0
__device__ float  g_part[(size_t)64 * 4 * 128 * 8]; // [qtile][slot][tok][8]
__device__ float2 g_trig[3 * 24];

// ---------------- PTX helpers ----------------
__device__ __forceinline__ uint32_t smem_u32(const void* p) {
    uint32_t a;
    asm("{ .reg .u64 t; cvta.to.shared.u64 t, %1; cvt.u32.u64 %0, t; }" : "=r"(a) : "l"(p));
    return a;
}
__device__ __forceinline__ void cp16(uint32_t s, const void* g) {
    asm volatile("cp.async.cg.shared.global [%0], [%1], 16;" :: "r"(s), "l"(g));
}
__device__ __forceinline__ void cp_commit() { asm volatile("cp.async.commit_group;"); }

__device__ __forceinline__ void ldsm_x4(uint32_t& r0, uint32_t& r1, uint32_t& r2, uint32_t& r3, uint32_t a) {
    asm volatile("ldmatrix.sync.aligned.m8n8.x4.shared.b16 {%0,%1,%2,%3}, [%4];"
                 : "=r"(r0), "=r"(r1), "=r"(r2), "=r"(r3) : "r"(a));
}
__device__ __forceinline__ void ldsm_x2(uint32_t& r0, uint32_t& r1, uint32_t a) {
    asm volatile("ldmatrix.sync.aligned.m8n8.x2.shared.b16 {%0,%1}, [%2];"
                 : "=r"(r0), "=r"(r1) : "r"(a));
}
__device__ __forceinline__ void mma16816(float* c, const uint32_t* a, const uint32_t* b) {
    asm volatile("mma.sync.aligned.m16n8k16.row.col.f32.f16.f16.f32 "
                 "{%0,%1,%2,%3}, {%4,%5,%6,%7}, {%8,%9}, {%0,%1,%2,%3};"
                 : "+f"(c[0]), "+f"(c[1]), "+f"(c[2]), "+f"(c[3])
                 : "r"(a[0]), "r"(a[1]), "r"(a[2]), "r"(a[3]), "r"(b[0]), "r"(b[1]));
}
__device__ __forceinline__ void sts16(uint32_t a, float v) {
    unsigned short u = __half_as_ushort(__float2half_rn(v));
    asm volatile("st.shared.b16 [%0], %1;" :: "r"(a), "h"(u));
}

// ---------------- quantum gates ----------------
__device__ __forceinline__ void ry_sc(float s, float c, int q, int lane,
        float& a0x, float& a0y, float& a1x, float& a1y)
{
    if (q == 5) {
        float n0x = c*a0x - s*a1x, n0y = c*a0y - s*a1y;
        float n1x = s*a0x + c*a1x, n1y = s*a0y + c*a1y;
        a0x = n0x; a0y = n0y; a1x = n1x; a1y = n1y;
    } else {
        int sh = 4 - q, m = 1 << sh;
        float o0x = __shfl_xor_sync(0xffffffffu, a0x, m);
        float o0y = __shfl_xor_sync(0xffffffffu, a0y, m);
        float o1x = __shfl_xor_sync(0xffffffffu, a1x, m);
        float o1y = __shfl_xor_sync(0xffffffffu, a1y, m);
        float sg = ((lane >> sh) & 1) ? s : -s;
        a0x = c*a0x + sg*o0x; a0y = c*a0y + sg*o0y;
        a1x = c*a1x + sg*o1x; a1y = c*a1y + sg*o1y;
    }
}

__device__ __forceinline__ void rz_sc(float s, float c, int q, int lane,
        float& a0x, float& a0y, float& a1x, float& a1y)
{
    if (q == 5) {
        float n0x = a0x*c + a0y*s, n0y = a0y*c - a0x*s;
        float n1x = a1x*c - a1y*s, n1y = a1y*c + a1x*s;
        a0x = n0x; a0y = n0y; a1x = n1x; a1y = n1y;
    } else {
        float t = ((lane >> (4 - q)) & 1) ? s : -s;
        float n0x = a0x*c - a0y*t, n0y = a0y*c + a0x*t;
        float n1x = a1x*c - a1y*t, n1y = a1y*c + a1x*t;
        a0x = n0x; a0y = n0y; a1x = n1x; a1y = n1y;
    }
}

__device__ __forceinline__ void cnot_ll(int csh, int tmask, int lane,
        float& a0x, float& a0y, float& a1x, float& a1y)
{
    float o0x = __shfl_xor_sync(0xffffffffu, a0x, tmask);
    float o0y = __shfl_xor_sync(0xffffffffu, a0y, tmask);
    float o1x = __shfl_xor_sync(0xffffffffu, a1x, tmask);
    float o1y = __shfl_xor_sync(0xffffffffu, a1y, tmask);
    if ((lane >> csh) & 1) { a0x = o0x; a0y = o0y; a1x = o1x; a1y = o1y; }
}

__device__ __forceinline__ void pqc_fwd(const float2* trig, int lane,
        float& a0x, float& a0y, float& a1x, float& a1y)
{
    #pragma unroll
    for (int l = 0; l < 2; l++) {
        #pragma unroll
        for (int q = 0; q < 6; q++) {
            float2 ty = trig[(l * 6 + q) * 2 + 0];
            ry_sc(ty.x, ty.y, q, lane, a0x, a0y, a1x, a1y);
            float2 tz = trig[(l * 6 + q) * 2 + 1];
            rz_sc(tz.x, tz.y, q, lane, a0x, a0y, a1x, a1y);
        }
        cnot_ll(4, 8, lane, a0x, a0y, a1x, a1y);
        cnot_ll(3, 4, lane, a0x, a0y, a1x, a1y);
        cnot_ll(2, 2, lane, a0x, a0y, a1x, a1y);
        cnot_ll(1, 1, lane, a0x, a0y, a1x, a1y);
        if (lane & 1) {
            float t;
            t = a0x; a0x = a1x; a1x = t;
            t = a0y; a0y = a1y; a1y = t;
        }
        a1x = __shfl_xor_sync(0xffffffffu, a1x, 16);
        a1y = __shfl_xor_sync(0xffffffffu, a1y, 16);
    }
}

__device__ __forceinline__ void pqc_inv(const float2* trig, int lane,
        float& a0x, float& a0y, float& a1x, float& a1y)
{
    #pragma unroll
    for (int l = 1; l >= 0; l--) {
        a1x = __shfl_xor_sync(0xffffffffu, a1x, 16);
        a1y = __shfl_xor_sync(0xffffffffu, a1y, 16);
        if (lane & 1) {
            float t;
            t = a0x; a0x = a1x; a1x = t;
            t = a0y; a0y = a1y; a1y = t;
        }
        cnot_ll(1, 1, lane, a0x, a0y, a1x, a1y);
        cnot_ll(2, 2, lane, a0x, a0y, a1x, a1y);
        cnot_ll(3, 4, lane, a0x, a0y, a1x, a1y);
        cnot_ll(4, 8, lane, a0x, a0y, a1x, a1y);
        #pragma unroll
        for (int q = 0; q < 6; q++) {
            float2 tz = trig[(l * 6 + q) * 2 + 1];
            rz_sc(-tz.x, tz.y, q, lane, a0x, a0y, a1x, a1y);
            float2 ty = trig[(l * 6 + q) * 2 + 0];
            ry_sc(-ty.x, ty.y, q, lane, a0x, a0y, a1x, a1y);
        }
    }
}

__global__ void trig_kernel(const float* __restrict__ pq,
                            const float* __restrict__ pk,
                            const float* __restrict__ pv)
{
    int i = threadIdx.x;
    if (i < 72) {
        int set = i / 24, r = i % 24;
        const float* p = (set == 0) ? pq : (set == 1) ? pk : pv;
        float s, c;
        sincosf(0.5f * p[r], &s, &c);
        g_trig[i] = make_float2(s, c);
    }
}

__global__ void prep_kernel(const float* __restrict__ x)
{
    int gw   = (blockIdx.x * blockDim.x + threadIdx.x) >> 5;
    int lane = threadIdx.x & 31;
    int set  = gw >> 13;            // 0=Q(phi), 1=K(psi), 2=V
    int tok  = gw & (NTOK - 1);

    float a0x = (lane == 0) ? 1.f : 0.f, a0y = 0.f, a1x = 0.f, a1y = 0.f;

    #pragma unroll
    for (int q = 0; q < 6; q++) {
        float s, c;
        sincosf(0.5f * x[tok * 6 + q], &s, &c);
        ry_sc(s, c, q, lane, a0x, a0y, a1x, a1y);
    }

    if (set == 0) {
        ((__half2*)g_a)[tok * 32 + lane] = __floats2half2_rn(a0x, a1x);
    } else if (set == 1) {
        pqc_fwd(g_trig + 24, lane, a0x, a0y, a1x, a1y);   // K-PQC
        pqc_inv(g_trig + 0,  lane, a0x, a0y, a1x, a1y);   // inverse Q-PQC
        ((__half2*)g_b)[(tok * 2 + 0) * 32 + lane] = __floats2half2_rn(a0x, a1x);
        ((__half2*)g_b)[(tok * 2 + 1) * 32 + lane] = __floats2half2_rn(a0y, a1y);
    } else {
        pqc_fwd(g_trig + 48, lane, a0x, a0y, a1x, a1y);   // V-PQC
        float p0 = a0x*a0x + a0y*a0y;
        float p1 = a1x*a1x + a1y*a1y;
        int d0 = lane * 2, d1 = lane * 2 + 1;
        #pragma unroll
        for (int q = 0; q < 6; q++) {
            float s0 = ((d0 >> (5 - q)) & 1) ? -1.f : 1.f;
            float s1 = ((d1 >> (5 - q)) & 1) ? -1.f : 1.f;
            float z = s0 * p0 + s1 * p1;
            #pragma unroll
            for (int o = 16; o; o >>= 1) z += __shfl_xor_sync(0xffffffffu, z, o);
            if (lane == 0) g_vt[q * NTOK + tok] = __float2half_rn(z);
        }
        if (lane == 0) {
            g_vt[6 * NTOK + tok] = __float2half_rn(1.f);   // ones row -> den
            g_vt[7 * NTOK + tok] = __float2half_rn(0.f);
        }
    }
}

// ---------------- fused attention ----------------
extern __shared__ char smx[];

// one 64-key chunk: 128 psi col-rows (16KB) + Vt 8 rows x 128B (1KB)
__device__ __forceinline__ void issue_chunk(uint32_t smb, uint32_t boff, uint32_t vtoff,
                                            int kb, int tid)
{
    #pragma unroll
    for (int it = 0; it < 5; it++) {
        int i = it * 256 + tid;
        if (i < 1024) {
            int row = i >> 3, ch = i & 7;
            cp16(smb + boff + row * 144 + ch * 16,
                 g_b + (size_t)(kb * 2 + row) * 64 + ch * 8);
        } else if (i < 1088) {
            int j = i - 1024, row = j >> 3, ch = j & 7;
            cp16(smb + vtoff + row * 144 + ch * 16,
                 g_vt + (size_t)row * NTOK + kb + ch * 8);
        }
    }
    cp_commit();
}

__device__ __forceinline__ void flush_O(char* sm, float O[2][4], int b, int q,
                                        int mwarp, int wcol, int lane, int tid)
{
    float2* red = (float2*)(sm + RED_OFF);
    __syncthreads();
    int r0 = mwarp + (lane >> 2);
    int cc = lane & 3;
    if (wcol == 0) {
        #pragma unroll
        for (int rt = 0; rt < 2; rt++) {
            red[(r0 + rt * 16) * 4 + cc]     = make_float2(O[rt][0], O[rt][1]);
            red[(r0 + rt * 16 + 8) * 4 + cc] = make_float2(O[rt][2], O[rt][3]);
        }
    }
    __syncthreads();
    if (wcol == 1) {
        #pragma unroll
        for (int rt = 0; rt < 2; rt++) {
            float2 v0 = red[(r0 + rt * 16) * 4 + cc];
            v0.x += O[rt][0]; v0.y += O[rt][1];
            red[(r0 + rt * 16) * 4 + cc] = v0;
            float2 v1 = red[(r0 + rt * 16 + 8) * 4 + cc];
            v1.x += O[rt][2]; v1.y += O[rt][3];
            red[(r0 + rt * 16 + 8) * 4 + cc] = v1;
        }
    }
    __syncthreads();
    if (tid < 128) {
        int slot = b - ((q * 128 + 1) * GCTAS - 1) / NUNITS;
        const float4* src = (const float4*)((const float*)(sm + RED_OFF) + tid * 8);
        float4* dst = (float4*)(g_part + ((size_t)(q * 4 + slot) * 128 + tid) * 8);
        dst[0] = src[0]; dst[1] = src[1];
    }
}

__global__ void __launch_bounds__(256, 1) attn_kernel()
{
    char* sm = smx;
    uint32_t smb = smem_u32(sm);
    int tid  = threadIdx.x;
    int wid  = tid >> 5, lane = tid & 31;
    int wrow = wid & 3, wcol = wid >> 2;      // warp grid 4x2
    int mwarp = wrow * 32;
    int b = blockIdx.x;
    int u0 = (NUNITS * b) / GCTAS;
    int u1 = (NUNITS * (b + 1)) / GCTAS;

    uint32_t pbase = smb + P_OFF + wid * 2560;

    // prologue: prefetch chunk u0 into its parity buffer
    {
        int p0 = u0 & 1;
        issue_chunk(smb, p0 ? B_OFF1 : B_OFF0, VT_OFF(p0), 64 * (u0 & 127), tid);
    }

    uint32_t afr[2][4][4];
    float O[2][4];
    int qcur = -1;
    int brow_l = wcol * 64 + (lane >> 4) * 8 + (lane & 7);
    int boffk  = ((lane >> 3) & 1) * 16;
    int l4 = lane & 15;

    for (int u = u0; u < u1; u++) {
        int q = u >> 7, p = u & 1;
        bool newq = (q != qcur);
        bool pref = (u + 1 < u1);

        if (newq) {
            if (qcur >= 0) flush_O(sm, O, b, qcur, mwarp, wcol, lane, tid);
            #pragma unroll
            for (int e = 0; e < 4; e++) {
                int i = e * 256 + tid, row = i >> 3, ch = i & 7;
                cp16(smb + A_OFF + row * 144 + ch * 16,
                     g_a + (size_t)(q * 128 + row) * 64 + ch * 8);
            }
            cp_commit();
            qcur = q;
        }
        if (pref)
            issue_chunk(smb, ((u + 1) & 1) ? B_OFF1 : B_OFF0, VT_OFF((u + 1) & 1),
                        64 * ((u + 1) & 127), tid);
        if (newq) {
            if (pref) asm volatile("cp.async.wait_group 1;" ::: "memory");
            else      asm volatile("cp.async.wait_group 0;" ::: "memory");
            __syncthreads();
            int rowa = mwarp + (lane & 15), offa = (lane >> 4) * 16;
            #pragma unroll
            for (int rt = 0; rt < 2; rt++)
                #pragma unroll
                for (int kt = 0; kt < 4; kt++)
                    ldsm_x4(afr[rt][kt][0], afr[rt][kt][1], afr[rt][kt][2], afr[rt][kt][3],
                            smb + A_OFF + (rowa + rt * 16) * 144 + kt * 32 + offa);
            #pragma unroll
            for (int rt = 0; rt < 2; rt++)
                #pragma unroll
                for (int e = 0; e < 4; e++) O[rt][e] = 0.f;
        }

        // ---- main GEMM on buffer p ----
        uint32_t boff = p ? B_OFF1 : B_OFF0;
        float acc[2][8][4];
        #pragma unroll
        for (int rt = 0; rt < 2; rt++)
            #pragma unroll
            for (int ct = 0; ct < 8; ct++)
                #pragma unroll
                for (int e = 0; e < 4; e++) acc[rt][ct][e] = 0.f;

        #pragma unroll
        for (int kt = 0; kt < 4; kt++) {
            uint32_t bfr[8][2];
            #pragma unroll
            for (int cp2 = 0; cp2 < 4; cp2++) {
                uint32_t r0, r1, r2, r3;
                ldsm_x4(r0, r1, r2, r3,
                        smb + boff + (brow_l + cp2 * 16) * 144 + kt * 32 + boffk);
                bfr[2*cp2][0] = r0; bfr[2*cp2][1] = r1;
                bfr[2*cp2+1][0] = r2; bfr[2*cp2+1][1] = r3;
            }
            #pragma unroll
            for (int ct = 0; ct < 8; ct++)
                #pragma unroll
                for (int rt = 0; rt < 2; rt++)
                    mma16816(acc[rt][ct], afr[rt][kt], bfr[ct]);
        }

        // ---- convert acc -> P (fp16 exp(logit)) in per-warp smem ----
        __syncwarp();
        #pragma unroll
        for (int ct = 0; ct < 8; ct++) {
            int key = ct * 4 + (lane & 3);
            #pragma unroll
            for (int rt = 0; rt < 2; rt++) {
                int r = rt * 16 + (lane >> 2);
                float l0 = fmaf(acc[rt][ct][0], acc[rt][ct][0], acc[rt][ct][1] * acc[rt][ct][1]);
                float l1 = fmaf(acc[rt][ct][2], acc[rt][ct][2], acc[rt][ct][3] * acc[rt][ct][3]);
                sts16(pbase + r * 80 + key * 2, __expf(l0));
                sts16(pbase + (r + 8) * 80 + key * 2, __expf(l1));
            }
        }
        __syncwarp();

        // ---- P(32x32) x Vt(32x8) GEMM into persistent O ----
        uint32_t vtb = smb + VT_OFF(p);
        #pragma unroll
        for (int kt2 = 0; kt2 < 2; kt2++) {
            uint32_t bb[2];
            ldsm_x2(bb[0], bb[1],
                    vtb + (l4 & 7) * 144 + wcol * 64 + kt2 * 32 + (l4 >> 3) * 16);
            #pragma unroll
            for (int rt2 = 0; rt2 < 2; rt2++) {
                uint32_t a4[4];
                ldsm_x4(a4[0], a4[1], a4[2], a4[3],
                        pbase + ((lane & 15) + rt2 * 16) * 80 + kt2 * 32 + (lane >> 4) * 16);
                mma16816(O[rt2], a4, bb);
            }
        }

        if (pref) {
            asm volatile("cp.async.wait_group 0;" ::: "memory");
            __syncthreads();
        }
    }
    flush_O(sm, O, b, qcur, mwarp, wcol, lane, tid);
}

__global__ void finalize_kernel(float* __restrict__ out)
{
    int i = blockIdx.x * blockDim.x + threadIdx.x;   // token
    int q = i >> 7, r = i & 127;
    int ca = ((q * 128 + 1)   * GCTAS - 1) / NUNITS;
    int cb = ((q * 128 + 128) * GCTAS - 1) / NUNITS;
    float a0 = 0.f, a1 = 0.f, a2 = 0.f, a3 = 0.f, a4 = 0.f, a5 = 0.f, dn = 0.f;
    for (int s = 0; s <= cb - ca; s++) {
        const float* p = g_part + ((size_t)(q * 4 + s) * 128 + r) * 8;
        a0 += p[0]; a1 += p[1]; a2 += p[2];
        a3 += p[3]; a4 += p[4]; a5 += p[5];
        dn += p[6];
    }
    float inv = 1.0f / dn;
    out[i * 6 + 0] = a0 * inv;
    out[i * 6 + 1] = a1 * inv;
    out[i * 6 + 2] = a2 * inv;
    out[i * 6 + 3] = a3 * inv;
    out[i * 6 + 4] = a4 * inv;
    out[i * 6 + 5] = a5 * inv;
}

extern "C" void kernel_launch(void* const* d_in, const int* in_sizes, int n_in,
                              void* d_out, int out_size)
{
    const float* x  = (const float*)d_in[0];
    const float* pq = (const float*)d_in[1];
    const float* pk = (const float*)d_in[2];
    const float* pv = (const float*)d_in[3];

    trig_kernel<<<1, 128>>>(pq, pk, pv);
    prep_kernel<<<(3 * NTOK) / 8, 256>>>(x);

    cudaFuncSetAttribute(attn_kernel, cudaFuncAttributeMaxDynamicSharedMemorySize, SMEM_TOTAL);
    attn_kernel<<<GCTAS, 256, SMEM_TOTAL>>>();

    finalize_kernel<<<NTOK / 256, 256>>>((float*)d_out);
}